// round 14
// baseline (speedup 1.0000x reference)
#include <cuda_runtime.h>
#include <cuda_fp16.h>

// Dims fixed by the reference: x is (B=8, T=2048, F=128) float32.
#define BB 8
#define TT 2048
#define FF 128
#define NN (BB * TT * FF)           // 2,097,152
#define NSITE (NN / 4)              // 524,288 f4-sites; site = (b<<16)|(t<<5)|f4
#define SB (TT * FF)                // 262144 (elem stride along B)
#define ST (FF)                     // 128    (elem stride along T)
#define SITE_B 65536                // site stride along B
#define SITE_T 32                   // site stride along T

#define TAU_F (1.0f / 6.0f)
#define NFUSED 28                   // updates #2..#29 (update #1 is k_first)

#define NTHREADS 256                // k_first / k_final
#define NT3 128                     // k_fused: 4 warps = 4 t-rows + 1 halo
#define TROWS 4

// Packed dual buffers: p0+p1 in one 16-B word per site, p2 in 8 B.
__device__ uint4 gA01[NSITE];
__device__ uint2 gA2[NSITE];
__device__ uint4 gB01[NSITE];
__device__ uint2 gB2[NSITE];
__device__ __half g_imgh[NN];

// ---------------- fp32 helpers (k_first / k_final only) --------------------
__device__ __forceinline__ float4 ld4(const float* __restrict__ p, int idx) {
    return *reinterpret_cast<const float4*>(p + idx);
}
__device__ __forceinline__ void st4(float* __restrict__ p, int idx, float4 v) {
    *reinterpret_cast<float4*>(p + idx) = v;
}
__device__ __forceinline__ float4 u2tof4(uint2 u) {
    __half2 h0 = *reinterpret_cast<__half2*>(&u.x);
    __half2 h1 = *reinterpret_cast<__half2*>(&u.y);
    float2 f0 = __half22float2(h0);
    float2 f1 = __half22float2(h1);
    return make_float4(f0.x, f0.y, f1.x, f1.y);
}
__device__ __forceinline__ uint2 f4tou2(float4 v) {
    __half2 h0 = __floats2half2_rn(v.x, v.y);
    __half2 h1 = __floats2half2_rn(v.z, v.w);
    uint2 u;
    u.x = *reinterpret_cast<unsigned*>(&h0);
    u.y = *reinterpret_cast<unsigned*>(&h1);
    return u;
}
__device__ __forceinline__ float4 f4sub(float4 a, float4 b) {
    return make_float4(a.x - b.x, a.y - b.y, a.z - b.z, a.w - b.w);
}
__device__ __forceinline__ float4 f4add(float4 a, float4 b) {
    return make_float4(a.x + b.x, a.y + b.y, a.z + b.z, a.w + b.w);
}

// ---------------- half2 helpers --------------------------------------------
struct H4 { __half2 lo, hi; };
__device__ __forceinline__ H4 ldH4(const __half* __restrict__ p, int idx) {
    uint2 u = *reinterpret_cast<const uint2*>(p + idx);
    H4 r;
    r.lo = *reinterpret_cast<__half2*>(&u.x);
    r.hi = *reinterpret_cast<__half2*>(&u.y);
    return r;
}
__device__ __forceinline__ unsigned h2u(__half2 h) {
    return *reinterpret_cast<unsigned*>(&h);
}
__device__ __forceinline__ __half2 u2h(unsigned u) {
    return *reinterpret_cast<__half2*>(&u);
}

// ---------------------------------------------------------------------------
// k_first: p = 0  =>  out = img, g = grad(img). Writes packed pA + img_h.
// ---------------------------------------------------------------------------
__global__ __launch_bounds__(NTHREADS)
void k_first(const float* __restrict__ img, const float* __restrict__ lam) {
    int tid = blockIdx.x * blockDim.x + threadIdx.x;   // f4 site
    if (tid >= NSITE) return;
    int lane = tid & 31;
    int t = (tid >> 5) & (TT - 1);
    int b = tid >> 16;
    int idx = tid * 4;

    float4 o = ld4(img, idx);
    *reinterpret_cast<uint2*>(g_imgh + idx) = f4tou2(o);

    float4 gb = make_float4(0, 0, 0, 0), gt = make_float4(0, 0, 0, 0), gf;
    if (b < BB - 1) gb = f4sub(ld4(img, idx + SB), o);
    if (t < TT - 1) gt = f4sub(ld4(img, idx + ST), o);
    float nx = __shfl_down_sync(0xffffffffu, o.x, 1);
    gf.x = o.y - o.x; gf.y = o.z - o.y; gf.z = o.w - o.z;
    gf.w = (lane < 31) ? (nx - o.w) : 0.0f;

    float tw = TAU_F / lam[0];
    float4 r0, r1, r2;
#define FIRST_UPD(c)                                                     \
    { float n = sqrtf(gb.c * gb.c + gt.c * gt.c + gf.c * gf.c);          \
      float inv = __fdividef(1.0f, n * tw + 1.0f);                       \
      r0.c = (-TAU_F * gb.c) * inv;                                      \
      r1.c = (-TAU_F * gt.c) * inv;                                      \
      r2.c = (-TAU_F * gf.c) * inv; }
    FIRST_UPD(x) FIRST_UPD(y) FIRST_UPD(z) FIRST_UPD(w)
#undef FIRST_UPD
    uint2 u0 = f4tou2(r0), u1 = f4tou2(r1);
    uint4 v; v.x = u0.x; v.y = u0.y; v.z = u1.x; v.w = u1.y;
    gA01[tid] = v;
    gA2[tid] = f4tou2(r2);
}

// Compute out = img + div(p) for a full b-column at (t, lane). Writes
// olo/ohi[8] (fp16x4 per b). gb's p0[b-1] term is carried in registers.
__device__ __forceinline__ void out_col(const uint4* __restrict__ q01,
                                        const uint2* __restrict__ q01h,
                                        const uint2* __restrict__ q2,
                                        int t, int lane,
                                        __half2* olo, __half2* ohi) {
    const __half zeroh = __float2half(0.0f);
    __half2 prev0lo, prev0hi;                 // p0 of b-1 (carry)
#pragma unroll
    for (int b = 0; b < BB; ++b) {
        int s = (b << 16) + (t << 5) + lane;
        uint4 u01 = q01[s];
        uint2 up2 = q2[s];
        H4 im = ldH4(g_imgh, s * 4);
        __half2 p0lo = u2h(u01.x), p0hi = u2h(u01.y);
        __half2 p1lo = u2h(u01.z), p1hi = u2h(u01.w);
        __half2 p2lo = u2h(up2.x), p2hi = u2h(up2.y);
        __half2 dlo = __hsub2(__hsub2(__hsub2(im.lo, p0lo), p1lo), p2lo);
        __half2 dhi = __hsub2(__hsub2(__hsub2(im.hi, p0hi), p1hi), p2hi);
        if (b > 0) {                          // + p0[b-1] from registers
            dlo = __hadd2(dlo, prev0lo);
            dhi = __hadd2(dhi, prev0hi);
        }
        if (t > 0) {                          // + p1[t-1] (global, L2/L1)
            uint2 nt = q01h[2 * (s - SITE_T) + 1];
            dlo = __hadd2(dlo, u2h(nt.x));
            dhi = __hadd2(dhi, u2h(nt.y));
        }
        // + p2[f-1]: shift p2 right one element across the warp row.
        unsigned prevw = __shfl_up_sync(0xffffffffu, h2u(p2hi), 1);
        __half pe3 = (lane > 0)
            ? __ushort_as_half((unsigned short)(prevw >> 16)) : zeroh;
        __half2 shlo = __halves2half2(pe3, __low2half(p2lo));
        __half2 shhi = __halves2half2(__high2half(p2lo), __low2half(p2hi));
        dlo = __hadd2(dlo, shlo);
        dhi = __hadd2(dhi, shhi);
        olo[b] = dlo;
        ohi[b] = dhi;
        prev0lo = p0lo;
        prev0hi = p0hi;
    }
}

// ---------------------------------------------------------------------------
// k_fused: one Chambolle step, column-per-thread.
// Block = 4 warps; warp w owns t-row t0+w (full B-column per thread).
// Warp 0 additionally computes the t-halo row t0+4 (smem only).
// gb + div's b-terms are in-register; only gt crosses warps (via smem).
// ---------------------------------------------------------------------------
template <bool A2B>
__global__ __launch_bounds__(NT3)
void k_fused(const float* __restrict__ lam) {
    const uint4* __restrict__ q01 = A2B ? gA01 : gB01;
    const uint2* __restrict__ q01h =
        reinterpret_cast<const uint2*>(A2B ? gA01 : gB01);
    const uint2* __restrict__ q2 = A2B ? gA2 : gB2;
    uint4* __restrict__ w01 = A2B ? gB01 : gA01;
    uint2* __restrict__ w2 = A2B ? gB2 : gA2;

    __shared__ uint2 s_out[(TROWS + 1) * BB * 32];      // 10 KB

    const int warp = threadIdx.x >> 5;
    const int lane = threadIdx.x & 31;                  // == f4 index
    const int t0 = blockIdx.x * TROWS;
    const int t = t0 + warp;                            // own row (always < TT)

    const float twf = TAU_F / lam[0];
    const __half2 tw2 = __float2half2_rn(twf);
    const __half2 one2 = __float2half2_rn(1.0f);
    const __half2 ntau2 = __float2half2_rn(-TAU_F);
    const __half2 zero2 = __float2half2_rn(0.0f);

    // Phase A: own row into registers + smem.
    __half2 olo[BB], ohi[BB];
    out_col(q01, q01h, q2, t, lane, olo, ohi);
#pragma unroll
    for (int b = 0; b < BB; ++b) {
        uint2 u; u.x = h2u(olo[b]); u.y = h2u(ohi[b]);
        s_out[(warp * BB + b) * 32 + lane] = u;
    }
    // Halo row t0+4 (warp 0), smem only. Warp-uniform guard.
    if (warp == 0 && t0 + TROWS < TT) {
        __half2 hlo[BB], hhi[BB];
        out_col(q01, q01h, q2, t0 + TROWS, lane, hlo, hhi);
#pragma unroll
        for (int b = 0; b < BB; ++b) {
            uint2 u; u.x = h2u(hlo[b]); u.y = h2u(hhi[b]);
            s_out[(TROWS * BB + b) * 32 + lane] = u;
        }
    }
    __syncthreads();

    // Phase B: gradients + p update for own row.
    const bool hasT = (t < TT - 1);
#pragma unroll
    for (int b = 0; b < BB; ++b) {
        int s = (b << 16) + (t << 5) + lane;
        __half2 lo = olo[b], hi = ohi[b];

        __half2 gblo = zero2, gbhi = zero2;
        if (b < BB - 1) {                     // in-register b-gradient
            gblo = __hsub2(olo[b + 1], lo);
            gbhi = __hsub2(ohi[b + 1], hi);
        }
        __half2 gtlo = zero2, gthi = zero2;
        if (hasT) {
            uint2 nu = s_out[((warp + 1) * BB + b) * 32 + lane];
            gtlo = __hsub2(u2h(nu.x), lo);
            gthi = __hsub2(u2h(nu.y), hi);
        }
        // gf: out shifted left one element; last element (f==127) -> 0.
        unsigned nextw = __shfl_down_sync(0xffffffffu, h2u(lo), 1);
        __half ne0 = (lane < 31)
            ? __ushort_as_half((unsigned short)(nextw & 0xffff))
            : __high2half(hi);                // makes gf.w == 0
        __half2 sllo = __halves2half2(__high2half(lo), __low2half(hi));
        __half2 slhi = __halves2half2(__high2half(hi), ne0);
        __half2 gflo = __hsub2(sllo, lo);
        __half2 gfhi = __hsub2(slhi, hi);

        __half2 n2lo = __hfma2(gblo, gblo,
                        __hfma2(gtlo, gtlo, __hmul2(gflo, gflo)));
        __half2 n2hi = __hfma2(gbhi, gbhi,
                        __hfma2(gthi, gthi, __hmul2(gfhi, gfhi)));
        __half2 invlo = h2rcp(__hfma2(h2sqrt(n2lo), tw2, one2));
        __half2 invhi = h2rcp(__hfma2(h2sqrt(n2hi), tw2, one2));

        uint4 u01 = q01[s];                   // L1 hit (loaded in Phase A)
        uint2 up2 = q2[s];
        __half2 a0lo = u2h(u01.x), a0hi = u2h(u01.y);
        __half2 a1lo = u2h(u01.z), a1hi = u2h(u01.w);
        __half2 a2lo = u2h(up2.x), a2hi = u2h(up2.y);

        uint4 vo;
        vo.x = h2u(__hmul2(__hfma2(gblo, ntau2, a0lo), invlo));
        vo.y = h2u(__hmul2(__hfma2(gbhi, ntau2, a0hi), invhi));
        vo.z = h2u(__hmul2(__hfma2(gtlo, ntau2, a1lo), invlo));
        vo.w = h2u(__hmul2(__hfma2(gthi, ntau2, a1hi), invhi));
        w01[s] = vo;
        uint2 vo2;
        vo2.x = h2u(__hmul2(__hfma2(gflo, ntau2, a2lo), invlo));
        vo2.y = h2u(__hmul2(__hfma2(gfhi, ntau2, a2hi), invhi));
        w2[s] = vo2;
    }
}

// ---------------------------------------------------------------------------
// k_final: out = img + div(pA) + bias[f]. fp32 math, packed pA layout.
// ---------------------------------------------------------------------------
__global__ __launch_bounds__(NTHREADS)
void k_final(const float* __restrict__ img, const float* __restrict__ bias,
             float* __restrict__ out) {
    int tid = blockIdx.x * blockDim.x + threadIdx.x;   // site
    if (tid >= NSITE) return;
    int lane = tid & 31;
    int t = (tid >> 5) & (TT - 1);
    int b = tid >> 16;
    int idx = tid * 4;

    const uint2* __restrict__ q01h = reinterpret_cast<const uint2*>(gA01);

    uint4 u01 = gA01[tid];
    uint2 up2 = gA2[tid];
    uint2 u0; u0.x = u01.x; u0.y = u01.y;
    uint2 u1; u1.x = u01.z; u1.y = u01.w;
    float4 a0 = u2tof4(u0);
    float4 a1 = u2tof4(u1);
    float4 a2 = u2tof4(up2);

    float4 d = ld4(img, idx);
    d = f4sub(f4sub(f4sub(d, a0), a1), a2);
    if (b > 0) d = f4add(d, u2tof4(q01h[2 * (tid - SITE_B)]));
    if (t > 0) d = f4add(d, u2tof4(q01h[2 * (tid - SITE_T) + 1]));
    float prevw = __shfl_up_sync(0xffffffffu, a2.w, 1);
    if (lane > 0) d.x += prevw;
    d.y += a2.x; d.z += a2.y; d.w += a2.z;

    d = f4add(d, ld4(bias, lane * 4));
    st4(out, idx, d);
}

extern "C" void kernel_launch(void* const* d_in, const int* in_sizes, int n_in,
                              void* d_out, int out_size) {
    const float* x   = (const float*)d_in[0];   // (8, 2048, 128)
    const float* lam = (const float*)d_in[1];   // (1, 1)
    const float* b   = (const float*)d_in[2];   // (1, 1, 128)
    float* out = (float*)d_out;

    const int vblocks = (NSITE + NTHREADS - 1) / NTHREADS;    // 2048
    const int fblocks = TT / TROWS;                           // 512

    k_first<<<vblocks, NTHREADS>>>(x, lam);

    for (int it = 0; it < NFUSED; ++it) {
        if ((it & 1) == 0)
            k_fused<true><<<fblocks, NT3>>>(lam);   // A -> B
        else
            k_fused<false><<<fblocks, NT3>>>(lam);  // B -> A
    }

    k_final<<<vblocks, NTHREADS>>>(x, b, out);
}

// round 15
// speedup vs baseline: 1.4827x; 1.4827x over previous
#include <cuda_runtime.h>
#include <cuda_fp16.h>

// Dims fixed by the reference: x is (B=8, T=2048, F=128) float32.
#define BB 8
#define TT 2048
#define FF 128
#define NN (BB * TT * FF)           // 2,097,152
#define SB (TT * FF)                // 262144
#define ST (FF)                     // 128

#define TAU_F (1.0f / 6.0f)
#define NFUSED 28                   // updates #2..#29 (update #1 is k_first)

#define TTILE 2                     // output T-rows per block (grid = 1024)
#define NWARP 8                     // warp w <-> batch b = w
#define NTHREADS (NWARP * 32)       // 256

// Ping-pong dual buffers + fp16 image copy. No runtime allocation.
__device__ __half g_pa0[NN], g_pa1[NN], g_pa2[NN];
__device__ __half g_pb0[NN], g_pb1[NN], g_pb2[NN];
__device__ __half g_imgh[NN];

// ---------------- fp32 helpers (k_first / k_final only) --------------------
__device__ __forceinline__ float4 ld4(const float* __restrict__ p, int idx) {
    return *reinterpret_cast<const float4*>(p + idx);
}
__device__ __forceinline__ void st4(float* __restrict__ p, int idx, float4 v) {
    *reinterpret_cast<float4*>(p + idx) = v;
}
__device__ __forceinline__ float4 u2tof4(uint2 u) {
    __half2 h0 = *reinterpret_cast<__half2*>(&u.x);
    __half2 h1 = *reinterpret_cast<__half2*>(&u.y);
    float2 f0 = __half22float2(h0);
    float2 f1 = __half22float2(h1);
    return make_float4(f0.x, f0.y, f1.x, f1.y);
}
__device__ __forceinline__ uint2 f4tou2(float4 v) {
    __half2 h0 = __floats2half2_rn(v.x, v.y);
    __half2 h1 = __floats2half2_rn(v.z, v.w);
    uint2 u;
    u.x = *reinterpret_cast<unsigned*>(&h0);
    u.y = *reinterpret_cast<unsigned*>(&h1);
    return u;
}
__device__ __forceinline__ float4 ldh4(const __half* __restrict__ p, int idx) {
    return u2tof4(*reinterpret_cast<const uint2*>(p + idx));
}
__device__ __forceinline__ void sth4(__half* __restrict__ p, int idx, float4 v) {
    *reinterpret_cast<uint2*>(p + idx) = f4tou2(v);
}
__device__ __forceinline__ float4 f4sub(float4 a, float4 b) {
    return make_float4(a.x - b.x, a.y - b.y, a.z - b.z, a.w - b.w);
}
__device__ __forceinline__ float4 f4add(float4 a, float4 b) {
    return make_float4(a.x + b.x, a.y + b.y, a.z + b.z, a.w + b.w);
}

// ---------------- half2 helpers --------------------------------------------
struct H4 { __half2 lo, hi; };
__device__ __forceinline__ H4 ldH4(const __half* __restrict__ p, int idx) {
    uint2 u = *reinterpret_cast<const uint2*>(p + idx);
    H4 r;
    r.lo = *reinterpret_cast<__half2*>(&u.x);
    r.hi = *reinterpret_cast<__half2*>(&u.y);
    return r;
}
__device__ __forceinline__ void stH4(__half* __restrict__ p, int idx, H4 v) {
    uint2 u;
    u.x = *reinterpret_cast<unsigned*>(&v.lo);
    u.y = *reinterpret_cast<unsigned*>(&v.hi);
    *reinterpret_cast<uint2*>(p + idx) = u;
}
__device__ __forceinline__ unsigned h2u(__half2 h) {
    return *reinterpret_cast<unsigned*>(&h);
}
__device__ __forceinline__ __half2 u2h(unsigned u) {
    return *reinterpret_cast<__half2*>(&u);
}

// ---------------------------------------------------------------------------
// k_first: p = 0  =>  out = img, g = grad(img). Writes pA (fp16) + img_h.
// ---------------------------------------------------------------------------
__global__ __launch_bounds__(NTHREADS)
void k_first(const float* __restrict__ img, const float* __restrict__ lam) {
    int tid = blockIdx.x * blockDim.x + threadIdx.x;   // float4 index
    if (tid >= NN / 4) return;
    int lane = tid & 31;
    int t = (tid >> 5) & (TT - 1);
    int b = tid >> 16;
    int idx = tid * 4;

    float4 o = ld4(img, idx);
    *reinterpret_cast<uint2*>(g_imgh + idx) = f4tou2(o);

    float4 gb = make_float4(0, 0, 0, 0), gt = make_float4(0, 0, 0, 0), gf;
    if (b < BB - 1) gb = f4sub(ld4(img, idx + SB), o);
    if (t < TT - 1) gt = f4sub(ld4(img, idx + ST), o);
    float nx = __shfl_down_sync(0xffffffffu, o.x, 1);
    gf.x = o.y - o.x; gf.y = o.z - o.y; gf.z = o.w - o.z;
    gf.w = (lane < 31) ? (nx - o.w) : 0.0f;

    float tw = TAU_F / lam[0];
    float4 r0, r1, r2;
#define FIRST_UPD(c)                                                     \
    { float n = sqrtf(gb.c * gb.c + gt.c * gt.c + gf.c * gf.c);          \
      float inv = __fdividef(1.0f, n * tw + 1.0f);                       \
      r0.c = (-TAU_F * gb.c) * inv;                                      \
      r1.c = (-TAU_F * gt.c) * inv;                                      \
      r2.c = (-TAU_F * gf.c) * inv; }
    FIRST_UPD(x) FIRST_UPD(y) FIRST_UPD(z) FIRST_UPD(w)
#undef FIRST_UPD
    sth4(g_pa0, idx, r0);
    sth4(g_pa1, idx, r1);
    sth4(g_pa2, idx, r2);
}

// ---------------------------------------------------------------------------
// k_fused: one Chambolle step, half2 SIMD, warp-per-b alignment.
// Warp w owns batch b=w for ALL phases:
//   Phase A: out rows trow=0..2 (t0..t0+2) -> registers; trow 0,1 also smem.
//            q1[t-1] for trow>=1 is the previous row's own a1 (register carry).
//   Phase B: rows trow=0,1; own out + gt-neighbor from registers; only the
//            cross-b gb term reads smem. p reloaded from global (L1 hits).
// ---------------------------------------------------------------------------
template <bool A2B>
__global__ __launch_bounds__(NTHREADS, 7)
void k_fused(const float* __restrict__ lam) {
    const __half* __restrict__ q0 = A2B ? g_pa0 : g_pb0;
    const __half* __restrict__ q1 = A2B ? g_pa1 : g_pb1;
    const __half* __restrict__ q2 = A2B ? g_pa2 : g_pb2;
    __half* __restrict__ w0 = A2B ? g_pb0 : g_pa0;
    __half* __restrict__ w1 = A2B ? g_pb1 : g_pa1;
    __half* __restrict__ w2 = A2B ? g_pb2 : g_pa2;

    __shared__ uint2 s_out[BB][TTILE][32];              // 4 KB (trow 0,1 only)

    const int b = threadIdx.x >> 5;                     // warp == batch
    const int lane = threadIdx.x & 31;                  // == f4 index
    const int t0 = blockIdx.x * TTILE;

    const float twf = TAU_F / lam[0];
    const __half2 tw2 = __float2half2_rn(twf);
    const __half2 one2 = __float2half2_rn(1.0f);
    const __half2 ntau2 = __float2half2_rn(-TAU_F);
    const __half2 zero2 = __float2half2_rn(0.0f);
    const __half zeroh = __float2half(0.0f);

    __half2 olo[TTILE + 1], ohi[TTILE + 1];
    olo[TTILE] = zero2; ohi[TTILE] = zero2;             // halo default
    __half2 a1plo = zero2, a1phi = zero2;               // q1 carry (t-1 term)

    // Phase A: rows trow = 0..2 of own b.
#pragma unroll
    for (int trow = 0; trow <= TTILE; ++trow) {
        int t = t0 + trow;
        if (t < TT) {                                   // warp-uniform guard
            int idx = b * SB + t * ST + lane * 4;
            H4 im = ldH4(g_imgh, idx);
            H4 a0 = ldH4(q0, idx);
            H4 a1 = ldH4(q1, idx);
            H4 a2 = ldH4(q2, idx);
            __half2 dlo = __hsub2(__hsub2(__hsub2(im.lo, a0.lo), a1.lo), a2.lo);
            __half2 dhi = __hsub2(__hsub2(__hsub2(im.hi, a0.hi), a1.hi), a2.hi);
            if (b > 0) {
                H4 nb = ldH4(q0, idx - SB);
                dlo = __hadd2(dlo, nb.lo); dhi = __hadd2(dhi, nb.hi);
            }
            if (trow == 0) {
                if (t > 0) {
                    H4 nt = ldH4(q1, idx - ST);
                    dlo = __hadd2(dlo, nt.lo); dhi = __hadd2(dhi, nt.hi);
                }
            } else {                                    // register carry
                dlo = __hadd2(dlo, a1plo); dhi = __hadd2(dhi, a1phi);
            }
            // + p2[f-1]: shift a2 right one element across the warp row.
            unsigned prevw = __shfl_up_sync(0xffffffffu, h2u(a2.hi), 1);
            __half pe3 = (lane > 0)
                ? __ushort_as_half((unsigned short)(prevw >> 16)) : zeroh;
            __half2 shlo = __halves2half2(pe3, __low2half(a2.lo));
            __half2 shhi = __halves2half2(__high2half(a2.lo), __low2half(a2.hi));
            dlo = __hadd2(dlo, shlo); dhi = __hadd2(dhi, shhi);

            olo[trow] = dlo; ohi[trow] = dhi;
            if (trow < TTILE) {
                uint2 u; u.x = h2u(dlo); u.y = h2u(dhi);
                s_out[b][trow][lane] = u;
            }
            a1plo = a1.lo; a1phi = a1.hi;
        }
    }
    __syncthreads();

    // Phase B: rows trow = 0,1 of own b.
#pragma unroll
    for (int trow = 0; trow < TTILE; ++trow) {
        int t = t0 + trow;
        int idx = b * SB + t * ST + lane * 4;
        __half2 lo = olo[trow], hi = ohi[trow];

        __half2 gblo = zero2, gbhi = zero2;
        if (b < BB - 1) {                               // cross-b via smem
            uint2 nu = s_out[b + 1][trow][lane];
            gblo = __hsub2(u2h(nu.x), lo);
            gbhi = __hsub2(u2h(nu.y), hi);
        }
        __half2 gtlo = zero2, gthi = zero2;
        if (t < TT - 1) {                               // own register row
            gtlo = __hsub2(olo[trow + 1], lo);
            gthi = __hsub2(ohi[trow + 1], hi);
        }
        // gf: out shifted left one element; last element (f==127) -> 0.
        unsigned nextw = __shfl_down_sync(0xffffffffu, h2u(lo), 1);
        __half ne0 = (lane < 31)
            ? __ushort_as_half((unsigned short)(nextw & 0xffff))
            : __high2half(hi);                          // makes gf.w == 0
        __half2 sllo = __halves2half2(__high2half(lo), __low2half(hi));
        __half2 slhi = __halves2half2(__high2half(hi), ne0);
        __half2 gflo = __hsub2(sllo, lo);
        __half2 gfhi = __hsub2(slhi, hi);

        __half2 n2lo = __hfma2(gblo, gblo,
                        __hfma2(gtlo, gtlo, __hmul2(gflo, gflo)));
        __half2 n2hi = __hfma2(gbhi, gbhi,
                        __hfma2(gthi, gthi, __hmul2(gfhi, gfhi)));
        __half2 invlo = h2rcp(__hfma2(h2sqrt(n2lo), tw2, one2));
        __half2 invhi = h2rcp(__hfma2(h2sqrt(n2hi), tw2, one2));

        H4 a0 = ldH4(q0, idx);                          // L1 hits (Phase A)
        H4 a1 = ldH4(q1, idx);
        H4 a2 = ldH4(q2, idx);
        H4 o0, o1, o2;
        o0.lo = __hmul2(__hfma2(gblo, ntau2, a0.lo), invlo);
        o0.hi = __hmul2(__hfma2(gbhi, ntau2, a0.hi), invhi);
        o1.lo = __hmul2(__hfma2(gtlo, ntau2, a1.lo), invlo);
        o1.hi = __hmul2(__hfma2(gthi, ntau2, a1.hi), invhi);
        o2.lo = __hmul2(__hfma2(gflo, ntau2, a2.lo), invlo);
        o2.hi = __hmul2(__hfma2(gfhi, ntau2, a2.hi), invhi);
        stH4(w0, idx, o0);
        stH4(w1, idx, o1);
        stH4(w2, idx, o2);
    }
}

// ---------------------------------------------------------------------------
// k_final: out = img + div(pA) + bias[f]. fp32 math.
// ---------------------------------------------------------------------------
__global__ __launch_bounds__(NTHREADS)
void k_final(const float* __restrict__ img, const float* __restrict__ bias,
             float* __restrict__ out) {
    int tid = blockIdx.x * blockDim.x + threadIdx.x;
    if (tid >= NN / 4) return;
    int lane = tid & 31;
    int t = (tid >> 5) & (TT - 1);
    int b = tid >> 16;
    int idx = tid * 4;

    float4 d = ld4(img, idx);
    float4 a0 = ldh4(g_pa0, idx);
    float4 a1 = ldh4(g_pa1, idx);
    float4 a2 = ldh4(g_pa2, idx);
    d = f4sub(f4sub(f4sub(d, a0), a1), a2);
    if (b > 0) d = f4add(d, ldh4(g_pa0, idx - SB));
    if (t > 0) d = f4add(d, ldh4(g_pa1, idx - ST));
    float prevw = __shfl_up_sync(0xffffffffu, a2.w, 1);
    if (lane > 0) d.x += prevw;
    d.y += a2.x; d.z += a2.y; d.w += a2.z;

    d = f4add(d, ld4(bias, lane * 4));
    st4(out, idx, d);
}

extern "C" void kernel_launch(void* const* d_in, const int* in_sizes, int n_in,
                              void* d_out, int out_size) {
    const float* x   = (const float*)d_in[0];   // (8, 2048, 128)
    const float* lam = (const float*)d_in[1];   // (1, 1)
    const float* b   = (const float*)d_in[2];   // (1, 1, 128)
    float* out = (float*)d_out;

    const int vblocks = (NN / 4 + NTHREADS - 1) / NTHREADS;   // 2048
    const int fblocks = TT / TTILE;                           // 1024

    k_first<<<vblocks, NTHREADS>>>(x, lam);

    for (int it = 0; it < NFUSED; ++it) {
        if ((it & 1) == 0)
            k_fused<true><<<fblocks, NTHREADS>>>(lam);   // A -> B
        else
            k_fused<false><<<fblocks, NTHREADS>>>(lam);  // B -> A
    }

    k_final<<<vblocks, NTHREADS>>>(x, b, out);
}